// round 10
// baseline (speedup 1.0000x reference)
#include <cuda_runtime.h>
#include <cuda_fp16.h>
#include <cstdint>

// Problem dims
#define NTOK   32768
#define HIDDEN 1024
#define INTER  768

// ---------------- scratch (static device memory; no allocs) ----------------
static __device__ __align__(128) __half g_Xh[(size_t)NTOK * HIDDEN];   // 64 MB
static __device__ __align__(128) __half g_Wg[INTER * HIDDEN];          // 1.5 MB
static __device__ __align__(128) __half g_Wu[INTER * HIDDEN];          // 1.5 MB
static __device__ __align__(128) __half g_Wd[HIDDEN * INTER];          // 1.5 MB
static __device__ __align__(128) __half g_H [(size_t)NTOK * INTER];    // 48 MB

// ---------------- helpers ----------------
__device__ __forceinline__ uint32_t smem_u32(const void* p) {
    uint32_t a;
    asm("{ .reg .u64 t; cvta.to.shared.u64 t, %1; cvt.u32.u64 %0, t; }" : "=r"(a) : "l"(p));
    return a;
}

#define SW128(o) ((uint32_t)(o) ^ ((((uint32_t)(o)) >> 3) & 0x70))

__device__ __forceinline__ void cp_async16(uint32_t saddr, const void* gaddr) {
    asm volatile("cp.async.cg.shared.global [%0], [%1], 16;\n" :: "r"(saddr), "l"(gaddr));
}
__device__ __forceinline__ void cp_commit() { asm volatile("cp.async.commit_group;\n" ::: "memory"); }
__device__ __forceinline__ void cp_wait1()  { asm volatile("cp.async.wait_group 1;\n" ::: "memory"); }

__device__ __forceinline__ void ldm_x4(uint32_t* r, uint32_t saddr) {
    asm volatile("ldmatrix.sync.aligned.m8n8.x4.shared.b16 {%0,%1,%2,%3}, [%4];"
                 : "=r"(r[0]), "=r"(r[1]), "=r"(r[2]), "=r"(r[3]) : "r"(saddr));
}

__device__ __forceinline__ void mma16816(float* c, const uint32_t* a, uint32_t b0, uint32_t b1) {
    asm volatile("mma.sync.aligned.m16n8k16.row.col.f32.f16.f16.f32 "
                 "{%0,%1,%2,%3}, {%4,%5,%6,%7}, {%8,%9}, {%0,%1,%2,%3};"
                 : "+f"(c[0]), "+f"(c[1]), "+f"(c[2]), "+f"(c[3])
                 : "r"(a[0]), "r"(a[1]), "r"(a[2]), "r"(a[3]), "r"(b0), "r"(b1));
}

// ---------------- conversion kernels ----------------
__global__ void k_conv_x(const float* __restrict__ X) {
    size_t n4 = (size_t)NTOK * HIDDEN / 4;
    size_t stride = (size_t)gridDim.x * blockDim.x;
    __half2* dst = reinterpret_cast<__half2*>(g_Xh);
    for (size_t i = (size_t)blockIdx.x * blockDim.x + threadIdx.x; i < n4; i += stride) {
        float4 v = reinterpret_cast<const float4*>(X)[i];
        dst[2 * i + 0] = __floats2half2_rn(v.x, v.y);
        dst[2 * i + 1] = __floats2half2_rn(v.z, v.w);
    }
}

__global__ void k_conv_w(const float* __restrict__ G, const float* __restrict__ U,
                         const float* __restrict__ D, const int* __restrict__ E) {
    int e = E[0];
    size_t base = (size_t)e * (INTER * HIDDEN);
    size_t n4 = (size_t)(INTER * HIDDEN) / 4;
    size_t stride = (size_t)gridDim.x * blockDim.x;
    __half2* wg = reinterpret_cast<__half2*>(g_Wg);
    __half2* wu = reinterpret_cast<__half2*>(g_Wu);
    __half2* wd = reinterpret_cast<__half2*>(g_Wd);
    for (size_t i = (size_t)blockIdx.x * blockDim.x + threadIdx.x; i < n4; i += stride) {
        float4 g = reinterpret_cast<const float4*>(G + base)[i];
        float4 u = reinterpret_cast<const float4*>(U + base)[i];
        float4 d = reinterpret_cast<const float4*>(D + base)[i];
        wg[2 * i + 0] = __floats2half2_rn(g.x, g.y);
        wg[2 * i + 1] = __floats2half2_rn(g.z, g.w);
        wu[2 * i + 0] = __floats2half2_rn(u.x, u.y);
        wu[2 * i + 1] = __floats2half2_rn(u.z, u.w);
        wd[2 * i + 0] = __floats2half2_rn(d.x, d.y);
        wd[2 * i + 1] = __floats2half2_rn(d.z, d.w);
    }
}

// ======================== fused gate+up GEMM ========================
// BM=128, BN=64, BK=64. 128 thr = 4 warps (2 x 2); warp tile 64 x 32 per matrix.
// 128 fp32 acc/thread. 3-stage cp.async, 2 CTAs/SM.
#define GU_BM 128
#define GU_BN 64
#define GU_BK 64
#define GU_STAGE (GU_BM * GU_BK * 2 + 2 * GU_BN * GU_BK * 2)   // 32768
#define GU_SMEM  (3 * GU_STAGE)                                 // 98304

__device__ __forceinline__ void gu_load_stage(uint32_t sstage, int m0, int n0, int k0, int tid) {
#pragma unroll
    for (int i = 0; i < 8; i++) {
        int idx = tid + i * 128;
        int r = idx >> 3, c = idx & 7;
        cp_async16(sstage + SW128(r * 128 + c * 16),
                   g_Xh + (size_t)(m0 + r) * HIDDEN + k0 + c * 8);
    }
#pragma unroll
    for (int i = 0; i < 4; i++) {
        int idx = tid + i * 128;
        int r = idx >> 3, c = idx & 7;
        uint32_t off = SW128(r * 128 + c * 16);
        cp_async16(sstage + GU_BM * GU_BK * 2 + off,
                   g_Wg + (size_t)(n0 + r) * HIDDEN + k0 + c * 8);
        cp_async16(sstage + GU_BM * GU_BK * 2 + GU_BN * GU_BK * 2 + off,
                   g_Wu + (size_t)(n0 + r) * HIDDEN + k0 + c * 8);
    }
}

__global__ void __launch_bounds__(128, 2) k_gateup() {
    extern __shared__ __align__(1024) char smem[];
    uint32_t su = smem_u32(smem);
    int tid = threadIdx.x, lane = tid & 31, wid = tid >> 5;
    int warp_m = wid >> 1, warp_n = wid & 1;   // 2 x 2; warp: 64 rows x 32 cols (per matrix)
    int m0 = blockIdx.x * GU_BM;
    int n0 = blockIdx.y * GU_BN;

    int lrow = lane & 15, lhi = lane >> 4;
    // SW128(raw ^ ks*32) == SW128(raw) ^ (ks*32) since raw bits 5-6 are zero
    uint32_t swA[4], swB[2];
#pragma unroll
    for (int mt = 0; mt < 4; mt++)
        swA[mt] = SW128((uint32_t)((warp_m * 64 + mt * 16 + lrow) * 128 + lhi * 16));
#pragma unroll
    for (int p = 0; p < 2; p++)
        swB[p] = SW128((uint32_t)((warp_n * 32 + p * 16 + lrow) * 128 + lhi * 16));

    float cg[4][4][4], cu[4][4][4];
#pragma unroll
    for (int mt = 0; mt < 4; mt++)
#pragma unroll
        for (int nt = 0; nt < 4; nt++)
#pragma unroll
            for (int i = 0; i < 4; i++) { cg[mt][nt][i] = 0.f; cu[mt][nt][i] = 0.f; }

    const int NK = HIDDEN / GU_BK;   // 16
    gu_load_stage(su + 0 * GU_STAGE, m0, n0, 0 * GU_BK, tid); cp_commit();
    gu_load_stage(su + 1 * GU_STAGE, m0, n0, 1 * GU_BK, tid); cp_commit();

    for (int k = 0; k < NK; k++) {
        cp_wait1();
        __syncthreads();
        int kp = k + 2;
        if (kp < NK) gu_load_stage(su + (kp % 3) * GU_STAGE, m0, n0, kp * GU_BK, tid);
        cp_commit();

        uint32_t sb  = su + (k % 3) * GU_STAGE;
        uint32_t sbg = sb + GU_BM * GU_BK * 2;
        uint32_t sbu = sbg + GU_BN * GU_BK * 2;

        uint32_t a[2][4], bg[2][2][4], bu[2][2][4];
        ldm_x4(bg[0][0], sbg + swB[0]);
        ldm_x4(bg[0][1], sbg + swB[1]);
        ldm_x4(bu[0][0], sbu + swB[0]);
        ldm_x4(bu[0][1], sbu + swB[1]);
        ldm_x4(a[0], sb + swA[0]);

#pragma unroll
        for (int ks = 0; ks < 4; ks++) {
            int kb = ks & 1;
#pragma unroll
            for (int mt = 0; mt < 4; mt++) {
                int s = ks * 4 + mt;
                if (s < 15) {
                    int ns = s + 1;
                    ldm_x4(a[ns & 1], sb + (swA[ns & 3] ^ ((uint32_t)(ns >> 2) * 32)));
                }
                // spread next-ks B prefetch: one ldm per mt
                if (ks < 3) {
                    uint32_t kx = (uint32_t)(ks + 1) * 32;
                    int nb = kb ^ 1;
                    if (mt == 0)      ldm_x4(bg[nb][0], sbg + (swB[0] ^ kx));
                    else if (mt == 1) ldm_x4(bg[nb][1], sbg + (swB[1] ^ kx));
                    else if (mt == 2) ldm_x4(bu[nb][0], sbu + (swB[0] ^ kx));
                    else              ldm_x4(bu[nb][1], sbu + (swB[1] ^ kx));
                }
#pragma unroll
                for (int nt = 0; nt < 4; nt++) {
                    int p = nt >> 1, hi = nt & 1;
                    mma16816(cg[mt][nt], a[s & 1], bg[kb][p][hi], bg[kb][p][2 + hi]);
                    mma16816(cu[mt][nt], a[s & 1], bu[kb][p][hi], bu[kb][p][2 + hi]);
                }
            }
        }
    }

    // epilogue: SiLU(gate)*up -> fp16 -> g_H
    int r0 = m0 + warp_m * 64 + (lane >> 2);
    int c0 = n0 + warp_n * 32 + (lane & 3) * 2;
#pragma unroll
    for (int mt = 0; mt < 4; mt++)
#pragma unroll
        for (int nt = 0; nt < 4; nt++) {
            int col = c0 + nt * 8;
#pragma unroll
            for (int half = 0; half < 2; half++) {
                int r = r0 + mt * 16 + half * 8;
                float g0 = cg[mt][nt][2 * half + 0], g1 = cg[mt][nt][2 * half + 1];
                float u0 = cu[mt][nt][2 * half + 0], u1 = cu[mt][nt][2 * half + 1];
                float h0 = (g0 / (1.0f + __expf(-g0))) * u0;
                float h1 = (g1 / (1.0f + __expf(-g1))) * u1;
                __half2 hh = __floats2half2_rn(h0, h1);
                *reinterpret_cast<__half2*>(g_H + (size_t)r * INTER + col) = hh;
            }
        }
}

// ======================== down GEMM ========================
// out = H @ Wd^T : [NTOK, HIDDEN] fp32. BM=128, BN=128, BK=64.
// 128 thr = 4 warps (2 x 2); warp tile 64 x 64; 128 fp32 acc/thread.
#define DN_BM 128
#define DN_BN 128
#define DN_BK 64
#define DN_STAGE (DN_BM * DN_BK * 2 + DN_BN * DN_BK * 2)   // 32768
#define DN_SMEM  (3 * DN_STAGE)                             // 98304

__device__ __forceinline__ void dn_load_stage(uint32_t sstage, int m0, int n0, int k0, int tid) {
#pragma unroll
    for (int i = 0; i < 8; i++) {
        int idx = tid + i * 128;
        int r = idx >> 3, c = idx & 7;
        uint32_t off = SW128(r * 128 + c * 16);
        cp_async16(sstage + off, g_H + (size_t)(m0 + r) * INTER + k0 + c * 8);
        cp_async16(sstage + DN_BM * DN_BK * 2 + off,
                   g_Wd + (size_t)(n0 + r) * INTER + k0 + c * 8);
    }
}

__global__ void __launch_bounds__(128, 2) k_down(float* __restrict__ out) {
    extern __shared__ __align__(1024) char smem[];
    uint32_t su = smem_u32(smem);
    int tid = threadIdx.x, lane = tid & 31, wid = tid >> 5;
    int warp_m = wid >> 1, warp_n = wid & 1;   // 2 x 2 -> warp tile 64 x 64
    int m0 = blockIdx.x * DN_BM;
    int n0 = blockIdx.y * DN_BN;

    int lrow = lane & 15, lhi = lane >> 4;
    uint32_t swA[4], swB[4];
#pragma unroll
    for (int mt = 0; mt < 4; mt++)
        swA[mt] = SW128((uint32_t)((warp_m * 64 + mt * 16 + lrow) * 128 + lhi * 16));
#pragma unroll
    for (int p = 0; p < 4; p++)
        swB[p] = SW128((uint32_t)((warp_n * 64 + p * 16 + lrow) * 128 + lhi * 16));

    float acc[4][8][4];
#pragma unroll
    for (int mt = 0; mt < 4; mt++)
#pragma unroll
        for (int nt = 0; nt < 8; nt++)
#pragma unroll
            for (int i = 0; i < 4; i++) acc[mt][nt][i] = 0.f;

    const int NK = INTER / DN_BK;    // 12
    dn_load_stage(su + 0 * DN_STAGE, m0, n0, 0 * DN_BK, tid); cp_commit();
    dn_load_stage(su + 1 * DN_STAGE, m0, n0, 1 * DN_BK, tid); cp_commit();

    for (int k = 0; k < NK; k++) {
        cp_wait1();
        __syncthreads();
        int kp = k + 2;
        if (kp < NK) dn_load_stage(su + (kp % 3) * DN_STAGE, m0, n0, kp * DN_BK, tid);
        cp_commit();

        uint32_t sa  = su + (k % 3) * DN_STAGE;
        uint32_t sbb = sa + DN_BM * DN_BK * 2;

        uint32_t a[2][4], b[2][4][4];
        ldm_x4(b[0][0], sbb + swB[0]);
        ldm_x4(b[0][1], sbb + swB[1]);
        ldm_x4(b[0][2], sbb + swB[2]);
        ldm_x4(b[0][3], sbb + swB[3]);
        ldm_x4(a[0], sa + swA[0]);

#pragma unroll
        for (int ks = 0; ks < 4; ks++) {
            int kb = ks & 1;
#pragma unroll
            for (int mt = 0; mt < 4; mt++) {
                int s = ks * 4 + mt;
                if (s < 15) {
                    int ns = s + 1;
                    ldm_x4(a[ns & 1], sa + (swA[ns & 3] ^ ((uint32_t)(ns >> 2) * 32)));
                }
                // spread next-ks B prefetch: one ldm per mt
                if (ks < 3) {
                    ldm_x4(b[kb ^ 1][mt], sbb + (swB[mt] ^ ((uint32_t)(ks + 1) * 32)));
                }
#pragma unroll
                for (int nt = 0; nt < 8; nt++) {
                    int p = nt >> 1, hi = nt & 1;
                    mma16816(acc[mt][nt], a[s & 1], b[kb][p][hi], b[kb][p][2 + hi]);
                }
            }
        }
    }

    // epilogue: fp32 out
    int r0 = m0 + warp_m * 64 + (lane >> 2);
    int c0 = n0 + warp_n * 64 + (lane & 3) * 2;
#pragma unroll
    for (int mt = 0; mt < 4; mt++)
#pragma unroll
        for (int nt = 0; nt < 8; nt++) {
            int col = c0 + nt * 8;
            int r = r0 + mt * 16;
            float2 v0 = make_float2(acc[mt][nt][0], acc[mt][nt][1]);
            float2 v1 = make_float2(acc[mt][nt][2], acc[mt][nt][3]);
            *reinterpret_cast<float2*>(out + (size_t)r * HIDDEN + col) = v0;
            *reinterpret_cast<float2*>(out + (size_t)(r + 8) * HIDDEN + col) = v1;
        }
}

// ---------------- launch ----------------
extern "C" void kernel_launch(void* const* d_in, const int* in_sizes, int n_in,
                              void* d_out, int out_size) {
    const float* X = (const float*)d_in[0];
    const float* G = (const float*)d_in[1];
    const float* U = (const float*)d_in[2];
    const float* D = (const float*)d_in[3];
    const int*   E = (const int*)d_in[4];
    float* out = (float*)d_out;

    cudaFuncSetAttribute(k_gateup, cudaFuncAttributeMaxDynamicSharedMemorySize, GU_SMEM);
    cudaFuncSetAttribute(k_down,   cudaFuncAttributeMaxDynamicSharedMemorySize, DN_SMEM);

    k_conv_w<<<384, 512>>>(G, U, D, E);
    k_conv_x<<<4096, 512>>>(X);
    k_gateup<<<dim3(NTOK / GU_BM, INTER / GU_BN), 128, GU_SMEM>>>();
    k_down<<<dim3(NTOK / DN_BM, HIDDEN / DN_BN), 128, DN_SMEM>>>(out);
    (void)in_sizes; (void)n_in; (void)out_size;
}

// round 14
// speedup vs baseline: 1.0206x; 1.0206x over previous
#include <cuda_runtime.h>
#include <cuda_fp16.h>
#include <cstdint>

// Problem dims
#define NTOK   32768
#define HIDDEN 1024
#define INTER  768

// ---------------- scratch (static device memory; no allocs) ----------------
static __device__ __align__(128) __half g_Xh[(size_t)NTOK * HIDDEN];   // 64 MB
static __device__ __align__(128) __half g_Wg[INTER * HIDDEN];          // 1.5 MB
static __device__ __align__(128) __half g_Wu[INTER * HIDDEN];          // 1.5 MB
static __device__ __align__(128) __half g_Wd[HIDDEN * INTER];          // 1.5 MB
static __device__ __align__(128) __half g_H [(size_t)NTOK * INTER];    // 48 MB

// ---------------- helpers ----------------
__device__ __forceinline__ uint32_t smem_u32(const void* p) {
    uint32_t a;
    asm("{ .reg .u64 t; cvta.to.shared.u64 t, %1; cvt.u32.u64 %0, t; }" : "=r"(a) : "l"(p));
    return a;
}

#define SW128(o) ((uint32_t)(o) ^ ((((uint32_t)(o)) >> 3) & 0x70))

__device__ __forceinline__ void cp_async16(uint32_t saddr, const void* gaddr) {
    asm volatile("cp.async.cg.shared.global [%0], [%1], 16;\n" :: "r"(saddr), "l"(gaddr));
}
__device__ __forceinline__ void cp_commit() { asm volatile("cp.async.commit_group;\n" ::: "memory"); }
__device__ __forceinline__ void cp_wait1()  { asm volatile("cp.async.wait_group 1;\n" ::: "memory"); }

__device__ __forceinline__ void ldm_x4(uint32_t* r, uint32_t saddr) {
    asm volatile("ldmatrix.sync.aligned.m8n8.x4.shared.b16 {%0,%1,%2,%3}, [%4];"
                 : "=r"(r[0]), "=r"(r[1]), "=r"(r[2]), "=r"(r[3]) : "r"(saddr));
}

__device__ __forceinline__ void mma16816(float* c, const uint32_t* a, uint32_t b0, uint32_t b1) {
    asm volatile("mma.sync.aligned.m16n8k16.row.col.f32.f16.f16.f32 "
                 "{%0,%1,%2,%3}, {%4,%5,%6,%7}, {%8,%9}, {%0,%1,%2,%3};"
                 : "+f"(c[0]), "+f"(c[1]), "+f"(c[2]), "+f"(c[3])
                 : "r"(a[0]), "r"(a[1]), "r"(a[2]), "r"(a[3]), "r"(b0), "r"(b1));
}

// ---------------- merged conversion kernel ----------------
// One grid-stride pass over X (fp32->fp16) and the 3 selected expert weight
// matrices. Index space in float4 units: [0, n4x) -> X, then G, U, D.
#define N4X ((size_t)NTOK * HIDDEN / 4)
#define N4W ((size_t)(INTER * HIDDEN) / 4)

__global__ void k_conv(const float* __restrict__ X,
                       const float* __restrict__ G, const float* __restrict__ U,
                       const float* __restrict__ D, const int* __restrict__ E) {
    int e = E[0];
    size_t wbase = (size_t)e * (INTER * HIDDEN) / 4;   // float4 offset into expert dim
    size_t total = N4X + 3 * N4W;
    size_t stride = (size_t)gridDim.x * blockDim.x;
    for (size_t i = (size_t)blockIdx.x * blockDim.x + threadIdx.x; i < total; i += stride) {
        const float4* src;
        __half2* dst;
        size_t j;
        if (i < N4X) {
            src = reinterpret_cast<const float4*>(X);         j = i;
            dst = reinterpret_cast<__half2*>(g_Xh);
        } else if (i < N4X + N4W) {
            src = reinterpret_cast<const float4*>(G) + wbase; j = i - N4X;
            dst = reinterpret_cast<__half2*>(g_Wg);
        } else if (i < N4X + 2 * N4W) {
            src = reinterpret_cast<const float4*>(U) + wbase; j = i - N4X - N4W;
            dst = reinterpret_cast<__half2*>(g_Wu);
        } else {
            src = reinterpret_cast<const float4*>(D) + wbase; j = i - N4X - 2 * N4W;
            dst = reinterpret_cast<__half2*>(g_Wd);
        }
        float4 v = src[j];
        dst[2 * j + 0] = __floats2half2_rn(v.x, v.y);
        dst[2 * j + 1] = __floats2half2_rn(v.z, v.w);
    }
}

// ======================== fused gate+up GEMM (R9/R5 structure, 256 thr) ========================
// BM=128, BN=64, BK=64. 256 thr = 8 warps (4 x 2). 3-stage cp.async, 2 CTAs/SM.
#define GU_BM 128
#define GU_BN 64
#define GU_BK 64
#define GU_STAGE (GU_BM * GU_BK * 2 + 2 * GU_BN * GU_BK * 2)   // 32768
#define GU_SMEM  (3 * GU_STAGE)                                 // 98304

__device__ __forceinline__ void gu_load_stage(uint32_t sstage, int m0, int n0, int k0, int tid) {
#pragma unroll
    for (int i = 0; i < 4; i++) {
        int idx = tid + i * 256;
        int r = idx >> 3, c = idx & 7;
        cp_async16(sstage + SW128(r * 128 + c * 16),
                   g_Xh + (size_t)(m0 + r) * HIDDEN + k0 + c * 8);
    }
#pragma unroll
    for (int i = 0; i < 2; i++) {
        int idx = tid + i * 256;
        int r = idx >> 3, c = idx & 7;
        uint32_t off = SW128(r * 128 + c * 16);
        cp_async16(sstage + GU_BM * GU_BK * 2 + off,
                   g_Wg + (size_t)(n0 + r) * HIDDEN + k0 + c * 8);
        cp_async16(sstage + GU_BM * GU_BK * 2 + GU_BN * GU_BK * 2 + off,
                   g_Wu + (size_t)(n0 + r) * HIDDEN + k0 + c * 8);
    }
}

__global__ void __launch_bounds__(256, 2) k_gateup() {
    extern __shared__ __align__(1024) char smem[];
    uint32_t su = smem_u32(smem);
    int tid = threadIdx.x, lane = tid & 31, wid = tid >> 5;
    int warp_m = wid >> 1, warp_n = wid & 1;
    int m0 = blockIdx.x * GU_BM;
    int n0 = blockIdx.y * GU_BN;

    int lrow = lane & 15, lhi = lane >> 4;
    // SW128(raw + ks*32) == SW128(raw) ^ (ks*32)  (raw bits 5-6 are zero)
    uint32_t swA[2], swB[2];
#pragma unroll
    for (int mt = 0; mt < 2; mt++)
        swA[mt] = SW128((uint32_t)((warp_m * 32 + mt * 16 + lrow) * 128 + lhi * 16));
#pragma unroll
    for (int p = 0; p < 2; p++)
        swB[p] = SW128((uint32_t)((warp_n * 32 + p * 16 + lrow) * 128 + lhi * 16));

    float cg[2][4][4], cu[2][4][4];
#pragma unroll
    for (int mt = 0; mt < 2; mt++)
#pragma unroll
        for (int nt = 0; nt < 4; nt++)
#pragma unroll
            for (int i = 0; i < 4; i++) { cg[mt][nt][i] = 0.f; cu[mt][nt][i] = 0.f; }

    const int NK = HIDDEN / GU_BK;   // 16
    gu_load_stage(su + 0 * GU_STAGE, m0, n0, 0 * GU_BK, tid); cp_commit();
    gu_load_stage(su + 1 * GU_STAGE, m0, n0, 1 * GU_BK, tid); cp_commit();

    for (int k = 0; k < NK; k++) {
        cp_wait1();
        __syncthreads();
        int kp = k + 2;
        if (kp < NK) gu_load_stage(su + (kp % 3) * GU_STAGE, m0, n0, kp * GU_BK, tid);
        cp_commit();

        uint32_t sb  = su + (k % 3) * GU_STAGE;
        uint32_t sbg = sb + GU_BM * GU_BK * 2;
        uint32_t sbu = sbg + GU_BN * GU_BK * 2;

        uint32_t a[2][4], bg[2][2][4], bu[2][2][4];
        ldm_x4(bg[0][0], sbg + swB[0]);
        ldm_x4(bg[0][1], sbg + swB[1]);
        ldm_x4(bu[0][0], sbu + swB[0]);
        ldm_x4(bu[0][1], sbu + swB[1]);
        ldm_x4(a[0], sb + swA[0]);

        // steps s = 0..7 : ks = s>>1, mt = s&1
#pragma unroll
        for (int s = 0; s < 8; s++) {
            int ks = s >> 1, mt = s & 1, kb = ks & 1;
            if (s < 7) {
                int ns = s + 1;
                ldm_x4(a[ns & 1], sb + (swA[ns & 1] ^ ((uint32_t)(ns >> 1) * 32)));
            }
            if (mt == 0 && ks < 3) {
                int nb = (ks + 1) & 1;
                uint32_t kx = (uint32_t)(ks + 1) * 32;
#pragma unroll
                for (int p = 0; p < 2; p++) {
                    ldm_x4(bg[nb][p], sbg + (swB[p] ^ kx));
                    ldm_x4(bu[nb][p], sbu + (swB[p] ^ kx));
                }
            }
#pragma unroll
            for (int nt = 0; nt < 4; nt++) {
                int p = nt >> 1, hi = nt & 1;
                mma16816(cg[mt][nt], a[s & 1], bg[kb][p][hi], bg[kb][p][2 + hi]);
                mma16816(cu[mt][nt], a[s & 1], bu[kb][p][hi], bu[kb][p][2 + hi]);
            }
        }
    }

    // epilogue: SiLU(gate)*up -> fp16 -> g_H
    int r0 = m0 + warp_m * 32 + (lane >> 2);
    int c0 = n0 + warp_n * 32 + (lane & 3) * 2;
#pragma unroll
    for (int mt = 0; mt < 2; mt++)
#pragma unroll
        for (int nt = 0; nt < 4; nt++) {
            int col = c0 + nt * 8;
#pragma unroll
            for (int half = 0; half < 2; half++) {
                int r = r0 + mt * 16 + half * 8;
                float g0 = cg[mt][nt][2 * half + 0], g1 = cg[mt][nt][2 * half + 1];
                float u0 = cu[mt][nt][2 * half + 0], u1 = cu[mt][nt][2 * half + 1];
                float h0 = (g0 / (1.0f + __expf(-g0))) * u0;
                float h1 = (g1 / (1.0f + __expf(-g1))) * u1;
                __half2 hh = __floats2half2_rn(h0, h1);
                *reinterpret_cast<__half2*>(g_H + (size_t)r * INTER + col) = hh;
            }
        }
}

// ======================== down GEMM (R10 big-tile, 128 thr) ========================
// out = H @ Wd^T : [NTOK, HIDDEN] fp32. BM=128, BN=128, BK=64.
// 128 thr = 4 warps (2 x 2); warp tile 64 x 64; 128 fp32 acc/thread.
#define DN_BM 128
#define DN_BN 128
#define DN_BK 64
#define DN_STAGE (DN_BM * DN_BK * 2 + DN_BN * DN_BK * 2)   // 32768
#define DN_SMEM  (3 * DN_STAGE)                             // 98304

__device__ __forceinline__ void dn_load_stage(uint32_t sstage, int m0, int n0, int k0, int tid) {
#pragma unroll
    for (int i = 0; i < 8; i++) {
        int idx = tid + i * 128;
        int r = idx >> 3, c = idx & 7;
        uint32_t off = SW128(r * 128 + c * 16);
        cp_async16(sstage + off, g_H + (size_t)(m0 + r) * INTER + k0 + c * 8);
        cp_async16(sstage + DN_BM * DN_BK * 2 + off,
                   g_Wd + (size_t)(n0 + r) * INTER + k0 + c * 8);
    }
}

__global__ void __launch_bounds__(128, 2) k_down(float* __restrict__ out) {
    extern __shared__ __align__(1024) char smem[];
    uint32_t su = smem_u32(smem);
    int tid = threadIdx.x, lane = tid & 31, wid = tid >> 5;
    int warp_m = wid >> 1, warp_n = wid & 1;   // 2 x 2 -> warp tile 64 x 64
    int m0 = blockIdx.x * DN_BM;
    int n0 = blockIdx.y * DN_BN;

    int lrow = lane & 15, lhi = lane >> 4;
    uint32_t swA[4], swB[4];
#pragma unroll
    for (int mt = 0; mt < 4; mt++)
        swA[mt] = SW128((uint32_t)((warp_m * 64 + mt * 16 + lrow) * 128 + lhi * 16));
#pragma unroll
    for (int p = 0; p < 4; p++)
        swB[p] = SW128((uint32_t)((warp_n * 64 + p * 16 + lrow) * 128 + lhi * 16));

    float acc[4][8][4];
#pragma unroll
    for (int mt = 0; mt < 4; mt++)
#pragma unroll
        for (int nt = 0; nt < 8; nt++)
#pragma unroll
            for (int i = 0; i < 4; i++) acc[mt][nt][i] = 0.f;

    const int NK = INTER / DN_BK;    // 12
    dn_load_stage(su + 0 * DN_STAGE, m0, n0, 0 * DN_BK, tid); cp_commit();
    dn_load_stage(su + 1 * DN_STAGE, m0, n0, 1 * DN_BK, tid); cp_commit();

    for (int k = 0; k < NK; k++) {
        cp_wait1();
        __syncthreads();
        int kp = k + 2;
        if (kp < NK) dn_load_stage(su + (kp % 3) * DN_STAGE, m0, n0, kp * DN_BK, tid);
        cp_commit();

        uint32_t sa  = su + (k % 3) * DN_STAGE;
        uint32_t sbb = sa + DN_BM * DN_BK * 2;

        uint32_t a[2][4], b[2][4][4];
        ldm_x4(b[0][0], sbb + swB[0]);
        ldm_x4(b[0][1], sbb + swB[1]);
        ldm_x4(b[0][2], sbb + swB[2]);
        ldm_x4(b[0][3], sbb + swB[3]);
        ldm_x4(a[0], sa + swA[0]);

#pragma unroll
        for (int ks = 0; ks < 4; ks++) {
            int kb = ks & 1;
#pragma unroll
            for (int mt = 0; mt < 4; mt++) {
                int s = ks * 4 + mt;
                if (s < 15) {
                    int ns = s + 1;
                    ldm_x4(a[ns & 1], sa + (swA[ns & 3] ^ ((uint32_t)(ns >> 2) * 32)));
                }
                if (ks < 3) {
                    ldm_x4(b[kb ^ 1][mt], sbb + (swB[mt] ^ ((uint32_t)(ks + 1) * 32)));
                }
#pragma unroll
                for (int nt = 0; nt < 8; nt++) {
                    int p = nt >> 1, hi = nt & 1;
                    mma16816(acc[mt][nt], a[s & 1], b[kb][p][hi], b[kb][p][2 + hi]);
                }
            }
        }
    }

    // epilogue: fp32 out
    int r0 = m0 + warp_m * 64 + (lane >> 2);
    int c0 = n0 + warp_n * 64 + (lane & 3) * 2;
#pragma unroll
    for (int mt = 0; mt < 4; mt++)
#pragma unroll
        for (int nt = 0; nt < 8; nt++) {
            int col = c0 + nt * 8;
            int r = r0 + mt * 16;
            float2 v0 = make_float2(acc[mt][nt][0], acc[mt][nt][1]);
            float2 v1 = make_float2(acc[mt][nt][2], acc[mt][nt][3]);
            *reinterpret_cast<float2*>(out + (size_t)r * HIDDEN + col) = v0;
            *reinterpret_cast<float2*>(out + (size_t)(r + 8) * HIDDEN + col) = v1;
        }
}

// ---------------- launch ----------------
extern "C" void kernel_launch(void* const* d_in, const int* in_sizes, int n_in,
                              void* d_out, int out_size) {
    const float* X = (const float*)d_in[0];
    const float* G = (const float*)d_in[1];
    const float* U = (const float*)d_in[2];
    const float* D = (const float*)d_in[3];
    const int*   E = (const int*)d_in[4];
    float* out = (float*)d_out;

    cudaFuncSetAttribute(k_gateup, cudaFuncAttributeMaxDynamicSharedMemorySize, GU_SMEM);
    cudaFuncSetAttribute(k_down,   cudaFuncAttributeMaxDynamicSharedMemorySize, DN_SMEM);

    k_conv<<<4736, 512>>>(X, G, U, D, E);
    k_gateup<<<dim3(NTOK / GU_BM, INTER / GU_BN), 256, GU_SMEM>>>();
    k_down<<<dim3(NTOK / DN_BM, HIDDEN / DN_BN), 128, DN_SMEM>>>(out);
    (void)in_sizes; (void)n_in; (void)out_size;
}